// round 3
// baseline (speedup 1.0000x reference)
#include <cuda_runtime.h>

#define N_NODES 8192
#define IN_FEAT 256
#define HO      256
#define NHEAD   4
#define NEG     0.2f
#define ECHUNK  1024

// ---------------- scratch (allocation-free: __device__ globals) ----------------
__device__ float    g_support[(size_t)N_NODES * HO];   // 8 MB
__device__ float    g_f1[NHEAD * N_NODES];
__device__ float    g_f2[NHEAD * N_NODES];
__device__ unsigned g_f1max[NHEAD];

// monotonic float<->uint encoding for atomicMax on signed floats
__device__ __forceinline__ unsigned fenc(float f) {
    unsigned u = __float_as_uint(f);
    return (u & 0x80000000u) ? ~u : (u | 0x80000000u);
}
__device__ __forceinline__ float fdec(unsigned u) {
    return (u & 0x80000000u) ? __uint_as_float(u & 0x7fffffffu) : __uint_as_float(~u);
}

// ---------------- Kernel 1: fused SGEMMs ----------------
// z==0:  g_support = X @ W                      ([8192,256] @ [256,256])
// z==1:  out       = X @ Pw^T + bias + proj_b  (Pw is [256,256] row-major)
__global__ __launch_bounds__(256) void gemm_kernel(
    const float* __restrict__ X, const float* __restrict__ W,
    const float* __restrict__ Pw, const float* __restrict__ bias,
    const float* __restrict__ proj_b, float* __restrict__ out)
{
    const bool second = (blockIdx.z != 0);
    __shared__ float As[8][128];
    __shared__ float Bs[8][128];

    const int tid  = threadIdx.x;
    const int row0 = blockIdx.y * 128;
    const int col0 = blockIdx.x * 128;
    const int tx   = tid & 15;    // 16 cols of threads
    const int ty   = tid >> 4;    // 16 rows of threads
    const int aRow = tid >> 1;    // 0..127
    const int aK4  = (tid & 1) * 4;
    const int bK   = tid >> 5;    // 0..7
    const int bN4  = (tid & 31) * 4;

    float acc[8][8];
#pragma unroll
    for (int i = 0; i < 8; i++)
#pragma unroll
        for (int j = 0; j < 8; j++) acc[i][j] = 0.f;

    for (int k0 = 0; k0 < IN_FEAT; k0 += 8) {
        // A tile: As[k][m]
        float4 a4 = *(const float4*)(X + (size_t)(row0 + aRow) * IN_FEAT + k0 + aK4);
        As[aK4 + 0][aRow] = a4.x; As[aK4 + 1][aRow] = a4.y;
        As[aK4 + 2][aRow] = a4.z; As[aK4 + 3][aRow] = a4.w;
        if (!second) {
            float4 b4 = *(const float4*)(W + (size_t)(k0 + bK) * HO + col0 + bN4);
            *(float4*)(&Bs[bK][bN4]) = b4;
        } else {
            // Bs[k][n] = Pw[col0+n][k0+k]  (transposed access, coalesced along k)
            float4 b4 = *(const float4*)(Pw + (size_t)(col0 + aRow) * IN_FEAT + k0 + aK4);
            Bs[aK4 + 0][aRow] = b4.x; Bs[aK4 + 1][aRow] = b4.y;
            Bs[aK4 + 2][aRow] = b4.z; Bs[aK4 + 3][aRow] = b4.w;
        }
        __syncthreads();
#pragma unroll
        for (int kk = 0; kk < 8; kk++) {
            float4 a0 = *(const float4*)(&As[kk][ty * 8]);
            float4 a1 = *(const float4*)(&As[kk][ty * 8 + 4]);
            float4 b0 = *(const float4*)(&Bs[kk][tx * 8]);
            float4 b1 = *(const float4*)(&Bs[kk][tx * 8 + 4]);
            float ar[8] = {a0.x, a0.y, a0.z, a0.w, a1.x, a1.y, a1.z, a1.w};
            float br[8] = {b0.x, b0.y, b0.z, b0.w, b1.x, b1.y, b1.z, b1.w};
#pragma unroll
            for (int i = 0; i < 8; i++)
#pragma unroll
                for (int j = 0; j < 8; j++) acc[i][j] += ar[i] * br[j];
        }
        __syncthreads();
    }

    float* C = second ? out : g_support;
#pragma unroll
    for (int i = 0; i < 8; i++) {
        int row = row0 + ty * 8 + i;
#pragma unroll
        for (int j = 0; j < 8; j += 4) {
            int col = col0 + tx * 8 + j;
            float4 v;
            v.x = acc[i][j]; v.y = acc[i][j + 1]; v.z = acc[i][j + 2]; v.w = acc[i][j + 3];
            if (second) {
                v.x += bias[col]     + proj_b[col];
                v.y += bias[col + 1] + proj_b[col + 1];
                v.z += bias[col + 2] + proj_b[col + 2];
                v.w += bias[col + 3] + proj_b[col + 3];
            }
            *(float4*)(C + (size_t)row * HO + col) = v;
        }
    }
}

// ---------------- Kernel 2a: reset per-head max (deterministic each launch) ----
__global__ void zero_max_kernel() {
    if (threadIdx.x < NHEAD) g_f1max[threadIdx.x] = 0u;  // smaller than any real encoding
}

// ---------------- Kernel 2: f1[h,n], f2[h,n], per-head max of f1 ---------------
// one warp per node row; 8 warps per block; 1024 blocks
__global__ __launch_bounds__(256) void f1f2_kernel(
    const float* __restrict__ wu, const float* __restrict__ wv)
{
    const int warp = threadIdx.x >> 5, lane = threadIdx.x & 31;
    const int n = blockIdx.x * 8 + warp;
    const float* sup = g_support + (size_t)n * HO;
    float v[8];
#pragma unroll
    for (int i = 0; i < 8; i++) v[i] = sup[lane + 32 * i];
#pragma unroll
    for (int h = 0; h < NHEAD; h++) {
        float u0 = wu[h * 64 + lane],  u1 = wu[h * 64 + 32 + lane];
        float w0 = wv[h * 64 + lane],  w1 = wv[h * 64 + 32 + lane];
        float p1 = v[2 * h] * u0 + v[2 * h + 1] * u1;
        float p2 = v[2 * h] * w0 + v[2 * h + 1] * w1;
#pragma unroll
        for (int s = 16; s; s >>= 1) {
            p1 += __shfl_xor_sync(0xffffffffu, p1, s);
            p2 += __shfl_xor_sync(0xffffffffu, p2, s);
        }
        if (lane == 0) {
            g_f1[h * N_NODES + n] = p1;
            g_f2[h * N_NODES + n] = p2;
            atomicMax(&g_f1max[h], fenc(p1));
        }
    }
}

// ---------------- Kernel 3: per-row sparse softmax + aggregation ---------------
// block = one row n, 256 threads: tid = h*64 + o  (matches output layout)
__global__ __launch_bounds__(256) void attn_kernel(
    const float* __restrict__ adj, float* __restrict__ out)
{
    const int n    = blockIdx.x;
    const int tid  = threadIdx.x;
    const int lane = tid & 31;

    __shared__ unsigned short list[N_NODES];     // 16 KB
    __shared__ float sm_e[ECHUNK * NHEAD];       // 16 KB, layout [j*4 + h]
    __shared__ float sm_part[256];
    __shared__ int   sm_cnt;
    __shared__ float sm_f2[NHEAD], sm_B[NHEAD], sm_den[NHEAD];

    if (tid == 0) sm_cnt = 0;
    if (tid < NHEAD) {
        float f2v = g_f2[tid * N_NODES + n];
        sm_f2[tid] = f2v;
        float lg = f2v + fdec(g_f1max[tid]);       // exact upper bound on row logits
        sm_B[tid] = lg > 0.f ? lg : NEG * lg;      // lrelu monotonic -> bound on w
    }
    __syncthreads();

    // --- compact nonzero columns (adj nonzeros are exactly 1.0) ---
    const float4* arow = (const float4*)(adj + (size_t)n * N_NODES);
    for (int c = tid; c < N_NODES / 4; c += 256) {       // uniform 8 iterations
        float4 a = arow[c];
#pragma unroll
        for (int s = 0; s < 4; s++) {
            float av = (s == 0) ? a.x : (s == 1) ? a.y : (s == 2) ? a.z : a.w;
            bool nz = (av != 0.f);
            unsigned mask = __ballot_sync(0xffffffffu, nz);
            if (mask) {
                int leader = __ffs(mask) - 1;
                int base = 0;
                if (lane == leader) base = atomicAdd(&sm_cnt, __popc(mask));
                base = __shfl_sync(0xffffffffu, base, leader);
                if (nz)
                    list[base + __popc(mask & ((1u << lane) - 1u))] =
                        (unsigned short)(c * 4 + s);
            }
        }
    }
    __syncthreads();
    const int nnz = sm_cnt;   // >= 1 (self loop)

    const int h4 = tid & 3;   // head for e-phase (constant per thread)
    const int h  = tid >> 6;  // head for aggregation
    const float f2e = sm_f2[h4];
    const float Be  = sm_B[h4];
    const float* __restrict__ f1h  = g_f1 + h4 * N_NODES;
    const float* __restrict__ supp = g_support;

    float dsum = 0.f, acc = 0.f;
    for (int start = 0; start < nnz; start += ECHUNK) {
        int cnt = min(ECHUNK, nnz - start);
        __syncthreads();   // previous chunk's sm_e fully consumed
        // e-phase: cooperative exp over (edge, head)
        for (int jj = tid; jj < cnt * 4; jj += 256) {
            int j = jj >> 2;                 // jj&3 == tid&3 == h4
            int idx = list[start + j];
            float lg = f1h[idx] + f2e;
            float w  = lg > 0.f ? lg : NEG * lg;
            float e  = __expf(w - Be);
            sm_e[jj] = e;
            dsum += e;
        }
        __syncthreads();
        // aggregation: coalesced support gathers (L2-resident), high MLP
#pragma unroll 16
        for (int j = 0; j < cnt; j++) {
            int idx = list[start + j];
            float e = sm_e[(j << 2) + h];
            acc += e * supp[((size_t)idx << 8) + tid];
        }
    }

    // denominator reduction per head class (tid & 3)
    sm_part[tid] = dsum;
    __syncthreads();
    if (tid < NHEAD) {
        float s = 0.f;
        for (int k = tid; k < 256; k += 4) s += sm_part[k];
        sm_den[tid] = s;
    }
    __syncthreads();

    out[(size_t)n * HO + tid] += acc / sm_den[h];
}

// ---------------- launch ----------------
extern "C" void kernel_launch(void* const* d_in, const int* in_sizes, int n_in,
                              void* d_out, int out_size)
{
    const float* X    = (const float*)d_in[0];  // inputs   [8192,256]
    const float* adj  = (const float*)d_in[1];  // adj_mat  [8192,8192]
    const float* W    = (const float*)d_in[2];  // weight   [256,256]
    const float* wu   = (const float*)d_in[3];  // weight_u [4,64,1]
    const float* wv   = (const float*)d_in[4];  // weight_v [4,64,1]
    const float* bias = (const float*)d_in[5];  // bias     [1,256]
    const float* Pw   = (const float*)d_in[6];  // proj_w   [256,256]
    const float* pb   = (const float*)d_in[7];  // proj_b   [256]
    float* out = (float*)d_out;                 // [8192,256] f32

    dim3 g1(HO / 128, N_NODES / 128, 2);
    gemm_kernel<<<g1, 256>>>(X, W, Pw, bias, pb, out);
    zero_max_kernel<<<1, 32>>>();
    f1f2_kernel<<<N_NODES / 8, 256>>>(wu, wv);
    attn_kernel<<<N_NODES, 256>>>(adj, out);
}